// round 14
// baseline (speedup 1.0000x reference)
#include <cuda_runtime.h>
#include <stdint.h>

#define NN   4096
#define NE   8192
#define TOT  (1u << 26)       // E*E
#define KEEP 16384            // K*E
#define CAP  32768

// ---- device scratch (no allocations allowed) ----
__device__ uint32_t g_adj[(NN * NN) / 32];   // 2MB adjacency bitmap: bit (src*4096+dst)
__device__ int      g_cnt_src[NN];
__device__ int      g_cnt_dst[NN];
__device__ int      g_num_neg;
__device__ unsigned g_kept_cnt;
__device__ uint32_t g_kept[CAP];

// ---------------- zero scratch ----------------
__global__ void k_zero() {
    unsigned i = blockIdx.x * blockDim.x + threadIdx.x;
    unsigned stride = gridDim.x * blockDim.x;
    for (unsigned w = i; w < (NN * NN) / 32; w += stride) g_adj[w] = 0u;
    if (i < NN) { g_cnt_src[i] = 0; g_cnt_dst[i] = 0; }
    if (i == 0) { g_num_neg = 0; g_kept_cnt = 0u; }
}

// ---------------- build histograms + adjacency bitmap ----------------
__global__ void k_build(const int* __restrict__ src, const int* __restrict__ dst) {
    int e = blockIdx.x * blockDim.x + threadIdx.x;
    if (e < NE) {
        int n = src[e] & (NN - 1);   // mask: protect scratch from bad ids
        int v = dst[e] & (NN - 1);
        atomicOr(&g_adj[(((unsigned)n << 12) | (unsigned)v) >> 5], 1u << (v & 31));
        atomicAdd(&g_cnt_src[n], 1);
        atomicAdd(&g_cnt_dst[v], 1);
    }
}

// ---------------- num_negatives = sum_{i,j} m[i,j] ----------------
// colsum(v) = E - cnt_src[v] - sum_{n!=v, adj(n,v)} cnt_src[n]
// num_neg   = sum_v cnt_dst[v] * colsum(v)
__global__ void k_numneg() {
    int v = blockIdx.x * blockDim.x + threadIdx.x;
    if (v >= NN) return;
    unsigned wsel = (unsigned)v >> 5;
    unsigned bit  = 1u << (v & 31);
    int inv = g_cnt_src[v];
    for (int n = 0; n < NN; n++) {
        uint32_t w = g_adj[((unsigned)n << 7) + wsel];   // n*128 + v/32 (warp-broadcast)
        if ((w & bit) && n != v) inv += g_cnt_src[n];
    }
    int colsum = NE - inv;
    atomicAdd(&g_num_neg, g_cnt_dst[v] * colsum);
}

// ---------------- threefry2x32 scan — PARTITIONABLE scheme ----------------
// key = (0, 42);  ks0=0, ks1=42, ks2 = 0 ^ 42 ^ 0x1BD11BDA = 0x1BD11BF0
// element t: counter64 = t -> (x0 = hi = 0, x1 = lo = t); bits[t] = o0 ^ o1
#define TFR(r) { x0 += x1; x1 = __funnelshift_l(x1, x1, (r)); x1 ^= x0; }

__device__ __forceinline__ void try_keep(uint32_t t,
                                         const int* __restrict__ src,
                                         const int* __restrict__ dst) {
    int i = (int)(t >> 13);       // row  (< 8192)
    int j = (int)(t & 8191u);     // col
    int n = __ldg(&src[i]) & (NN - 1);
    int v = __ldg(&dst[j]) & (NN - 1);
    if (n != v) {
        uint32_t w = g_adj[(((unsigned)n << 12) | (unsigned)v) >> 5];
        if (!((w >> (v & 31)) & 1u)) {
            unsigned p = atomicAdd(&g_kept_cnt, 1u);
            if (p < CAP) g_kept[p] = t;
        }
    }
}

__global__ void k_scan(const int* __restrict__ src, const int* __restrict__ dst) {
    // keep_prob = fl32(2 / (num_neg // E)); u < kp  <=>  (bits>>9) < ceil(kp * 2^23)
    int ratio = g_num_neg >> 13;
    float kp = __fdiv_rn(2.0f, (float)ratio);
    uint32_t thresh = (uint32_t)ceilf(kp * 8388608.0f);

    unsigned stride = gridDim.x * blockDim.x;
    for (uint32_t t = blockIdx.x * blockDim.x + threadIdx.x; t < TOT; t += stride) {
        uint32_t x0 = 0u, x1 = t + 42u;       // x0 = hi + ks0 = 0, x1 = lo + ks1
        TFR(13) TFR(15) TFR(26) TFR(6)
        x0 += 42u;          x1 += 0x1BD11BF1u;   // ks1 ; ks2+1
        TFR(17) TFR(29) TFR(16) TFR(24)
        x0 += 0x1BD11BF0u;  x1 += 2u;            // ks2 ; ks0+2
        TFR(13) TFR(15) TFR(26) TFR(6)
                            x1 += 45u;           // ks0 ; ks1+3
        TFR(17) TFR(29) TFR(16) TFR(24)
        x0 += 42u;          x1 += 0x1BD11BF4u;   // ks1 ; ks2+4
        TFR(13) TFR(15) TFR(26) TFR(6)
        x0 += 0x1BD11BF0u;  x1 += 5u;            // ks2 ; ks0+5
        if (((x0 ^ x1) >> 9) < thresh) try_keep(t, src, dst);
    }
}

// ---------------- pad defaults (fill_value=0 -> flat idx 0 -> src[0], dst[0]) ----------------
// OUTPUT IS FLOAT32: node ids (< 4096) are exactly representable.
__global__ void k_fill(const int* __restrict__ src, const int* __restrict__ dst,
                       float* __restrict__ out) {
    int k = blockIdx.x * blockDim.x + threadIdx.x;
    if (k < KEEP) {
        out[k]        = (float)src[0];
        out[KEEP + k] = (float)dst[0];
    }
}

// ---------------- rank kept indices (ascending flat index) and emit ----------------
__global__ void k_rank(const int* __restrict__ src, const int* __restrict__ dst,
                       float* __restrict__ out) {
    __shared__ uint32_t tile[4096];
    unsigned cnt = min(g_kept_cnt, (unsigned)CAP);
    unsigned idx = blockIdx.x * blockDim.x + threadIdx.x;
    uint32_t myt = (idx < cnt) ? g_kept[idx] : 0xFFFFFFFFu;
    unsigned rank = 0;
    for (unsigned base = 0; base < cnt; base += 4096u) {
        unsigned m = min(4096u, cnt - base);
        __syncthreads();
        for (unsigned k = threadIdx.x; k < m; k += blockDim.x) tile[k] = g_kept[base + k];
        __syncthreads();
        if (idx < cnt) {
            for (unsigned k = 0; k < m; k++) rank += (tile[k] < myt) ? 1u : 0u;
        }
    }
    if (idx < cnt && rank < KEEP) {
        out[rank]        = (float)src[myt >> 13];
        out[KEEP + rank] = (float)dst[myt & 8191u];
    }
}

extern "C" void kernel_launch(void* const* d_in, const int* in_sizes, int n_in,
                              void* d_out, int out_size) {
    // Inputs: node_feature (262144 f32), edge_src (8192 i32), edge_dst (8192 i32).
    // Robust to both dict order [feat, src, dst] and alphabetical [dst, src, feat]:
    // edge_src sits at absolute index 1 in both; node_feature is the unique
    // 262144-element input; edge_dst is the remaining 8192-element input.
    int feat_idx = 0;
    for (int i = 0; i < n_in; i++)
        if (in_sizes[i] == NN * 64) feat_idx = i;
    int dst_idx = -1;
    for (int i = 0; i < n_in; i++)
        if (i != feat_idx && i != 1) { dst_idx = i; break; }
    if (dst_idx < 0) dst_idx = 2;

    const int* src = (const int*)d_in[1];
    const int* dst = (const int*)d_in[dst_idx];
    float* out = (float*)d_out;

    k_zero  <<<512, 256>>>();
    k_build <<<(NE + 255) / 256, 256>>>(src, dst);
    k_numneg<<<NN / 256, 256>>>();
    k_scan  <<<2368, 256>>>(src, dst);
    k_fill  <<<(KEEP + 255) / 256, 256>>>(src, dst, out);
    k_rank  <<<CAP / 256, 256>>>(src, dst, out);
}

// round 15
// speedup vs baseline: 2.3164x; 2.3164x over previous
#include <cuda_runtime.h>
#include <stdint.h>

#define NN     4096
#define NE     8192
#define TOT    (1u << 26)     // E*E
#define KEEP   16384          // K*E
#define NBUCK  16384          // buckets on t>>12 (4096 t-values each, lambda~1)
#define SLOTS  16             // P(bucket > 16) ~ 1e-15 per bucket at lambda=1

// ---- device scratch (no allocations allowed) ----
__device__ uint32_t g_adj[(NN * NN) / 32];    // 2MB adjacency bitmap
__device__ uint32_t g_claim[(NN * NN) / 32];  // 2MB dedup-claim bitmap
__device__ int      g_cnt_src[NN];
__device__ int      g_cnt_dst[NN];
__device__ int      g_inv[NN];
__device__ int      g_num_neg;
__device__ unsigned g_hist[NBUCK];
__device__ unsigned g_pref[NBUCK];
__device__ uint32_t g_bucket[NBUCK * SLOTS];

// ---------------- zero scratch ----------------
__global__ void k_zero() {
    unsigned i = blockIdx.x * blockDim.x + threadIdx.x;
    unsigned stride = gridDim.x * blockDim.x;
    for (unsigned w = i; w < (NN * NN) / 32; w += stride) { g_adj[w] = 0u; g_claim[w] = 0u; }
    for (unsigned w = i; w < NBUCK; w += stride) g_hist[w] = 0u;
    if (i < NN) { g_cnt_src[i] = 0; g_cnt_dst[i] = 0; g_inv[i] = 0; }
    if (i == 0) g_num_neg = 0;
}

// ---------------- histograms + adjacency bitmap ----------------
__global__ void k_build(const int* __restrict__ src, const int* __restrict__ dst) {
    int e = blockIdx.x * blockDim.x + threadIdx.x;
    if (e < NE) {
        int n = src[e] & (NN - 1), v = dst[e] & (NN - 1);
        unsigned idx = ((unsigned)n << 12) | (unsigned)v;
        atomicOr(&g_adj[idx >> 5], 1u << (idx & 31));
        atomicAdd(&g_cnt_src[n], 1);
        atomicAdd(&g_cnt_dst[v], 1);
    }
}

// ---------------- inv[v] = sum over DISTINCT (n,v) in adj, n!=v, of cnt_src[n] ----------------
// dedup over the 8192 edges via claim bitmap (needs cnt_src final -> runs after k_build)
__global__ void k_inv(const int* __restrict__ src, const int* __restrict__ dst) {
    int e = blockIdx.x * blockDim.x + threadIdx.x;
    if (e < NE) {
        int n = src[e] & (NN - 1), v = dst[e] & (NN - 1);
        unsigned idx = ((unsigned)n << 12) | (unsigned)v;
        unsigned bit = 1u << (idx & 31);
        unsigned old = atomicOr(&g_claim[idx >> 5], bit);
        if (!(old & bit) && n != v) atomicAdd(&g_inv[v], g_cnt_src[n]);
    }
}

// ---------------- num_neg = sum_v cnt_dst[v] * (E - cnt_src[v] - inv[v]) ----------------
__global__ void k_neg() {
    int v = blockIdx.x * blockDim.x + threadIdx.x;
    if (v < NN) atomicAdd(&g_num_neg, g_cnt_dst[v] * (NE - g_cnt_src[v] - g_inv[v]));
}

// ---------------- threefry2x32 scan — partitionable scheme ----------------
// key = (0, 42); ks0=0, ks1=42, ks2 = 0^42^0x1BD11BDA = 0x1BD11BF0
// element t: (x0 = hi = 0, x1 = lo = t); bits[t] = o0 ^ o1
// Adds routed to the FMA pipe via IMAD with runtime 'one' (alu pipe was at 88%).
#define ROTX(r) { x1 = __funnelshift_l(x1, x1, (r)); x1 ^= x0; }
__device__ __forceinline__ uint32_t addm(uint32_t a, uint32_t b, uint32_t one) {
    uint32_t d;
    asm("mad.lo.u32 %0, %1, %2, %3;" : "=r"(d) : "r"(a), "r"(one), "r"(b));
    return d;
}
#define TFR(r) { x0 = addm(x0, x1, one); ROTX(r) }

__device__ __forceinline__ void try_keep(uint32_t t,
                                         const int* __restrict__ src,
                                         const int* __restrict__ dst) {
    int n = __ldg(&src[t >> 13]);
    int v = __ldg(&dst[t & 8191u]);
    if (n != v) {
        uint32_t w = g_adj[(((unsigned)n << 12) | (unsigned)v) >> 5];
        if (!((w >> (v & 31)) & 1u)) {
            unsigned b = t >> 12;
            unsigned p = atomicAdd(&g_hist[b], 1u);
            if (p < SLOTS) g_bucket[b * SLOTS + p] = t;
        }
    }
}

#define SCAN_BLOCKS 2048
#define SCAN_ITERS  128    // 2048*256*128 = 2^26 exactly

__global__ void k_scan(const int* __restrict__ src, const int* __restrict__ dst,
                       uint32_t one) {
    // keep_prob = fl32(2/(num_neg//E)); u < kp  <=>  bits < ceil(kp*2^23) << 9
    int ratio = g_num_neg >> 13;
    float kp = __fdiv_rn(2.0f, (float)ratio);
    uint32_t thresh9 = ((uint32_t)ceilf(kp * 8388608.0f)) << 9;

    uint32_t kA = 42u,          kB = 0x1BD11BF1u;
    uint32_t kC = 0x1BD11BF0u,  kD = 2u;
    uint32_t kE = 45u;
    uint32_t kF = 0x1BD11BF4u,  kG = 5u;

    uint32_t t = blockIdx.x * blockDim.x + threadIdx.x;
    #pragma unroll 4
    for (int it = 0; it < SCAN_ITERS; it++) {
        uint32_t x1 = addm(t, kA, one);     // lo + ks1
        uint32_t x0 = x1;                   // round 1: x0(=0) += x1
        ROTX(13) TFR(15) TFR(26) TFR(6)
        x0 = addm(x0, kA, one);  x1 = addm(x1, kB, one);   // ks1 ; ks2+1
        TFR(17) TFR(29) TFR(16) TFR(24)
        x0 = addm(x0, kC, one);  x1 = addm(x1, kD, one);   // ks2 ; ks0+2
        TFR(13) TFR(15) TFR(26) TFR(6)
                                 x1 = addm(x1, kE, one);   // ks0 ; ks1+3
        TFR(17) TFR(29) TFR(16) TFR(24)
        x0 = addm(x0, kA, one);  x1 = addm(x1, kF, one);   // ks1 ; ks2+4
        TFR(13) TFR(15) TFR(26) TFR(6)
        x0 = addm(x0, kC, one);  x1 = addm(x1, kG, one);   // ks2 ; ks0+5
        if ((x0 ^ x1) < thresh9) try_keep(t, src, dst);
        t += SCAN_BLOCKS * 256u;
    }
}

// ---------------- exclusive prefix over 16384 bucket counts (1 block) ----------------
__global__ void k_prefix() {
    __shared__ unsigned sh[1024];
    unsigned i = threadIdx.x;
    unsigned loc[16], s = 0;
    #pragma unroll
    for (int j = 0; j < 16; j++) { loc[j] = g_hist[i * 16 + j]; s += loc[j]; }
    sh[i] = s; __syncthreads();
    for (int d = 1; d < 1024; d <<= 1) {
        unsigned v = (i >= (unsigned)d) ? sh[i - d] : 0u;
        __syncthreads();
        sh[i] += v;
        __syncthreads();
    }
    unsigned run = (i > 0) ? sh[i - 1] : 0u;
    #pragma unroll
    for (int j = 0; j < 16; j++) { g_pref[i * 16 + j] = run; run += loc[j]; }
}

// ---------------- pad defaults (fill_value=0 -> flat idx 0 -> src[0], dst[0]) ----------------
__global__ void k_fill(const int* __restrict__ src, const int* __restrict__ dst,
                       float* __restrict__ out) {
    int k = blockIdx.x * blockDim.x + threadIdx.x;
    if (k < KEEP) {
        out[k]        = (float)src[0];
        out[KEEP + k] = (float)dst[0];
    }
}

// ---------------- per-bucket sort (tiny) + emit at global rank ----------------
__global__ void k_place(const int* __restrict__ src, const int* __restrict__ dst,
                        float* __restrict__ out) {
    unsigned b = blockIdx.x * blockDim.x + threadIdx.x;
    if (b >= NBUCK) return;
    unsigned c = min(g_hist[b], (unsigned)SLOTS);
    uint32_t v[SLOTS];
    for (unsigned i = 0; i < c; i++) v[i] = g_bucket[b * SLOTS + i];
    for (unsigned i = 1; i < c; i++) {            // insertion sort (c ~ 1-3)
        uint32_t x = v[i]; int j = (int)i - 1;
        while (j >= 0 && v[j] > x) { v[j + 1] = v[j]; j--; }
        v[j + 1] = x;
    }
    unsigned base = g_pref[b];
    for (unsigned i = 0; i < c; i++) {
        unsigned r = base + i;
        if (r < KEEP) {
            uint32_t t = v[i];
            out[r]        = (float)__ldg(&src[t >> 13]);
            out[KEEP + r] = (float)__ldg(&dst[t & 8191u]);
        }
    }
}

extern "C" void kernel_launch(void* const* d_in, const int* in_sizes, int n_in,
                              void* d_out, int out_size) {
    // edge_src is index 1 under both dict and alphabetical ordering;
    // node_feature is the unique 262144-element input; edge_dst is the rest.
    int feat_idx = 0;
    for (int i = 0; i < n_in; i++)
        if (in_sizes[i] == NN * 64) feat_idx = i;
    int dst_idx = -1;
    for (int i = 0; i < n_in; i++)
        if (i != feat_idx && i != 1) { dst_idx = i; break; }
    if (dst_idx < 0) dst_idx = 2;

    const int* src = (const int*)d_in[1];
    const int* dst = (const int*)d_in[dst_idx];
    float* out = (float*)d_out;

    k_zero  <<<1024, 256>>>();
    k_build <<<(NE + 255) / 256, 256>>>(src, dst);
    k_inv   <<<(NE + 255) / 256, 256>>>(src, dst);
    k_neg   <<<NN / 256, 256>>>();
    k_scan  <<<SCAN_BLOCKS, 256>>>(src, dst, 1u);
    k_prefix<<<1, 1024>>>();
    k_fill  <<<(KEEP + 255) / 256, 256>>>(src, dst, out);
    k_place <<<NBUCK / 256, 256>>>(src, dst, out);
}